// round 13
// baseline (speedup 1.0000x reference)
#include <cuda_runtime.h>
#include <cuda_bf16.h>
#include <math.h>
#include <stdint.h>

#define Bz   8
#define Cc   256
#define Hh   64
#define Ww   64
#define HW   (Hh*Ww)
#define Ee   4
#define Dd   4
#define CRr  16
#define GIN  (2*Cc+16)
#define NPAIR 16

#define NTIL   256
#define NPOS   36
#define VSLAB  (Cc*NTIL)
#define USLAB  (Cc*Cc)
#define UPLANE (Ee*NPOS*USLAB)
#define WKT    256
#define WKCH   64
#define WNCH   (WKT/WKCH)
#define SIMG   (66*67)

#define SA_STR 72
#define SB_STR 136
#define A_PL   (128*SA_STR*2)
#define B_PL   (64*SB_STR*2)
#define STG_BYTES (2*A_PL + 2*B_PL)
#define SMEM_TOTAL (2*STG_BYTES)

__device__ float    g_bufB[NPAIR*Cc*HW];
__device__ float    g_bufC[NPAIR*Cc*HW];
__device__ __align__(16) uint16_t g_Uh[4*UPLANE];
__device__ __align__(16) uint16_t g_Ul[4*UPLANE];
__device__ __align__(16) uint16_t g_Vh[NPAIR*NPOS*VSLAB];
__device__ __align__(16) uint16_t g_Vl[NPAIR*NPOS*VSLAB];
__device__ float    g_M [NPAIR*NPOS*VSLAB];
__device__ float g_xavg[Bz*Cc];
__device__ float g_xmax[Bz*Cc];
__device__ float g_stat1[NPAIR*Cc];
__device__ float g_stat2[NPAIR*Cc];
__device__ int   g_pairs[NPAIR];
__device__ float g_wpair[NPAIR];
__device__ float g_g1[NPAIR];
__device__ float g_ca[NPAIR*Cc];
__device__ float g_sain[NPAIR*2*HW];
__device__ float g_sa[NPAIR*HW];

__device__ __forceinline__ float sigmoidf_(float x) { return 1.f / (1.f + __expf(-x)); }
__device__ __forceinline__ float gelu_tanh(float v) {
    float x3 = v * v * v;
    return 0.5f * v * (1.f + tanhf(0.7978845608028654f * (v + 0.044715f * x3)));
}
__device__ __forceinline__ void split_hilo(float v, uint16_t& h, uint16_t& l) {
    __nv_bfloat16 hb = __float2bfloat16(v);
    float r = v - __bfloat162float(hb);
    h = __bfloat16_as_ushort(hb);
    l = __bfloat16_as_ushort(__float2bfloat16(r));
}
__device__ __forceinline__ uint32_t sptr(const void* p) {
    return (uint32_t)__cvta_generic_to_shared(p);
}

#define CP_ASYNC16(dst, src) \
    asm volatile("cp.async.cg.shared.global [%0], [%1], 16;" :: "r"(dst), "l"(src))
#define CP_COMMIT() asm volatile("cp.async.commit_group;" ::: "memory")
#define CP_WAIT0()  asm volatile("cp.async.wait_group 0;" ::: "memory")

#define LDSM4(r, addr) \
    asm volatile("ldmatrix.sync.aligned.m8n8.x4.shared.b16 {%0,%1,%2,%3}, [%4];" \
        : "=r"((r)[0]), "=r"((r)[1]), "=r"((r)[2]), "=r"((r)[3]) : "r"(addr))
#define LDSM4T(r, addr) \
    asm volatile("ldmatrix.sync.aligned.m8n8.x4.trans.shared.b16 {%0,%1,%2,%3}, [%4];" \
        : "=r"((r)[0]), "=r"((r)[1]), "=r"((r)[2]), "=r"((r)[3]) : "r"(addr))
#define MMA16816(d, a, b0_, b1_) \
    asm volatile("mma.sync.aligned.m16n8k16.row.col.f32.bf16.bf16.f32 " \
        "{%0,%1,%2,%3}, {%4,%5,%6,%7}, {%8,%9}, {%0,%1,%2,%3};" \
        : "+f"((d)[0]), "+f"((d)[1]), "+f"((d)[2]), "+f"((d)[3]) \
        : "r"((a)[0]), "r"((a)[1]), "r"((a)[2]), "r"((a)[3]), "r"(b0_), "r"(b1_))

// ---------------- paired tile input transform: 2 x-adjacent tiles/thread -----
// s: padded 66x(67) channel. p in 0..127 (ty=p>>3, txp=p&7). vbase0 includes t0.
__device__ __forceinline__ void tile_to_V_pair(const float* s, int p, size_t vbase0,
                                               uint16_t* __restrict__ Vh,
                                               uint16_t* __restrict__ Vl) {
    int ty = p >> 3, txp = p & 7;
    const float* sp = s + (4*ty)*67 + 8*txp;
    float w[6][10];
    #pragma unroll
    for (int c = 0; c < 10; c++) {
        float d0=sp[0*67+c], d1=sp[1*67+c], d2=sp[2*67+c],
              d3=sp[3*67+c], d4=sp[4*67+c], d5=sp[5*67+c];
        w[0][c] = 4.f*d0 - 5.f*d2 + d4;
        w[1][c] = -4.f*d1 - 4.f*d2 + d3 + d4;
        w[2][c] =  4.f*d1 - 4.f*d2 - d3 + d4;
        w[3][c] = -2.f*d1 - d2 + 2.f*d3 + d4;
        w[4][c] =  2.f*d1 - d2 - 2.f*d3 + d4;
        w[5][c] =  4.f*d1 - 5.f*d3 + d5;
    }
    #pragma unroll
    for (int r = 0; r < 6; r++) {
        float v0[6], v1[6];
        {
            float d0=w[r][0], d1=w[r][1], d2=w[r][2], d3=w[r][3], d4=w[r][4], d5=w[r][5];
            v0[0] = 4.f*d0 - 5.f*d2 + d4;
            v0[1] = -4.f*d1 - 4.f*d2 + d3 + d4;
            v0[2] =  4.f*d1 - 4.f*d2 - d3 + d4;
            v0[3] = -2.f*d1 - d2 + 2.f*d3 + d4;
            v0[4] =  2.f*d1 - d2 - 2.f*d3 + d4;
            v0[5] =  4.f*d1 - 5.f*d3 + d5;
        }
        {
            float d0=w[r][4], d1=w[r][5], d2=w[r][6], d3=w[r][7], d4=w[r][8], d5=w[r][9];
            v1[0] = 4.f*d0 - 5.f*d2 + d4;
            v1[1] = -4.f*d1 - 4.f*d2 + d3 + d4;
            v1[2] =  4.f*d1 - 4.f*d2 - d3 + d4;
            v1[3] = -2.f*d1 - d2 + 2.f*d3 + d4;
            v1[4] =  2.f*d1 - d2 - 2.f*d3 + d4;
            v1[5] =  4.f*d1 - 5.f*d3 + d5;
        }
        #pragma unroll
        for (int c = 0; c < 6; c++) {
            uint16_t h0, l0, h1, l1;
            split_hilo(v0[c], h0, l0);
            split_hilo(v1[c], h1, l1);
            size_t o = vbase0 + (size_t)(r*6 + c) * VSLAB;
            *(uint32_t*)(Vh + o) = (uint32_t)h0 | ((uint32_t)h1 << 16);
            *(uint32_t*)(Vl + o) = (uint32_t)l0 | ((uint32_t)l1 << 16);
        }
    }
}

// ---------------- weight transform body --------------------------------------
__device__ __forceinline__ void wtrans_body(const float* __restrict__ w, int idx,
                                            uint16_t* __restrict__ Uh,
                                            uint16_t* __restrict__ Ul) {
    int ci = idx & 255, co = (idx >> 8) & 255, e = idx >> 16;
    const float* g = w + (size_t)idx * 9;
    float q[3][3];
    #pragma unroll
    for (int i = 0; i < 3; i++)
        #pragma unroll
        for (int j = 0; j < 3; j++) q[i][j] = g[i*3 + j];
    const float S6 = 1.f/6.f, S24 = 1.f/24.f;
    float t[6][3];
    #pragma unroll
    for (int c = 0; c < 3; c++) {
        float a = q[0][c], b = q[1][c], d = q[2][c];
        t[0][c] = 0.25f * a;
        t[1][c] = -S6 * (a + b + d);
        t[2][c] = -S6 * (a - b + d);
        t[3][c] = S24 * (a + 2.f*b + 4.f*d);
        t[4][c] = S24 * (a - 2.f*b + 4.f*d);
        t[5][c] = d;
    }
    #pragma unroll
    for (int r = 0; r < 6; r++) {
        float a = t[r][0], b = t[r][1], d = t[r][2];
        float uu[6];
        uu[0] = 0.25f * a;
        uu[1] = -S6 * (a + b + d);
        uu[2] = -S6 * (a - b + d);
        uu[3] = S24 * (a + 2.f*b + 4.f*d);
        uu[4] = S24 * (a - 2.f*b + 4.f*d);
        uu[5] = d;
        #pragma unroll
        for (int c = 0; c < 6; c++) {
            uint16_t hh, ll; split_hilo(uu[c], hh, ll);
            size_t o = ((size_t)(e*NPOS + r*6 + c) * Cc + co) * 256 + ci;
            Uh[o] = hh; Ul[o] = ll;
        }
    }
}

// ---------------- prep: conv1 wtrans (blocks 0..1023) + itransx (1024..2047) --
__global__ void prep_kernel(const float* __restrict__ w1, const float* __restrict__ x,
                            uint16_t* __restrict__ Uh, uint16_t* __restrict__ Ul,
                            uint16_t* __restrict__ Vh, uint16_t* __restrict__ Vl) {
    __shared__ float s[2][SIMG];
    int tid = threadIdx.x;
    if (blockIdx.x < 1024) {
        wtrans_body(w1, blockIdx.x * 256 + tid, Uh, Ul);
        return;
    }
    int bi = blockIdx.x - 1024;
    int c2 = bi & 127, b = bi >> 7;
    int ch = tid >> 7, lt = tid & 127;
    int c = c2*2 + ch;
    float* sc = s[ch];
    for (int i = lt; i < SIMG; i += 128) sc[i] = 0.f;
    __syncthreads();
    const float* xc = x + ((size_t)b*Cc + c)*HW;
    for (int i = lt; i < HW; i += 128)
        sc[((i>>6) + 1)*67 + (i & 63) + 1] = xc[i];
    __syncthreads();
    int t0 = (lt >> 3)*16 + 2*(lt & 7);
    size_t vbase = (size_t)b*NPOS*VSLAB + (size_t)c*256 + t0;
    tile_to_V_pair(sc, lt, vbase, Vh, Vl);
}

// ---------------- remaining 3 weight transforms in one launch -----------------
__global__ void wtrans3_kernel(const float* __restrict__ wa, const float* __restrict__ wb,
                               const float* __restrict__ wc,
                               uint16_t* __restrict__ Uh, uint16_t* __restrict__ Ul) {
    int cv = blockIdx.y;   // 0..2 -> planes 1..3
    const float* w = (cv == 0) ? wa : (cv == 1) ? wb : wc;
    wtrans_body(w, blockIdx.x * 256 + threadIdx.x,
                Uh + (size_t)(cv + 1)*UPLANE, Ul + (size_t)(cv + 1)*UPLANE);
}

// ---------------- Winograd GEMM (bf16x3) --------------------------------------
__global__ __launch_bounds__(512, 1) void wgemm_kernel(
    const uint16_t* __restrict__ Uh, const uint16_t* __restrict__ Ul,
    const uint16_t* __restrict__ Vh, const uint16_t* __restrict__ Vl,
    float* __restrict__ M, int vByBatch)
{
    int zb = blockIdx.z;
    int pair = zb / NPOS, pos = zb - pair*NPOS;
    int pe = g_pairs[pair];
    int e = pe & 3;
    int vslot = vByBatch ? (pe >> 2) : pair;
    int cob = blockIdx.y * 128;
    int tb  = blockIdx.x * 128;

    const uint16_t* Ahp = Uh + ((size_t)(e*NPOS + pos) * Cc + cob) * 256;
    const uint16_t* Alp = Ul + ((size_t)(e*NPOS + pos) * Cc + cob) * 256;
    const uint16_t* Bhp = Vh + (size_t)(vslot*NPOS + pos) * VSLAB + tb;
    const uint16_t* Blp = Vl + (size_t)(vslot*NPOS + pos) * VSLAB + tb;

    extern __shared__ __align__(16) char smem[];
    int tid  = threadIdx.x;
    int lane = tid & 31, wid = tid >> 5;
    int wco  = (wid & 3) * 32;
    int wpx  = (wid >> 2) * 32;
    int coG = tid >> 3, jG = tid & 7;

    float acc[2][4][4];
    #pragma unroll
    for (int mt = 0; mt < 2; mt++)
        #pragma unroll
        for (int nt = 0; nt < 4; nt++)
            #pragma unroll
            for (int q = 0; q < 4; q++) acc[mt][nt][q] = 0.f;

    #define W_ISSUE(c, s) do { \
        char* _ab = smem + (s)*STG_BYTES; \
        size_t _ka = (size_t)(c) * WKCH + jG*8; \
        CP_ASYNC16(sptr(_ab + coG*144 + jG*16),             Ahp + (size_t)coG*256 + _ka); \
        CP_ASYNC16(sptr(_ab + (coG+64)*144 + jG*16),        Ahp + (size_t)(coG+64)*256 + _ka); \
        CP_ASYNC16(sptr(_ab + A_PL + coG*144 + jG*16),      Alp + (size_t)coG*256 + _ka); \
        CP_ASYNC16(sptr(_ab + A_PL + (coG+64)*144 + jG*16), Alp + (size_t)(coG+64)*256 + _ka); \
        char* _bb = _ab + 2*A_PL; \
        size_t _kb = (size_t)((c)*WKCH + coG) * 256; \
        CP_ASYNC16(sptr(_bb + coG*272 + jG*16),         Bhp + _kb + jG*8); \
        CP_ASYNC16(sptr(_bb + coG*272 + jG*16 + 128),   Bhp + _kb + jG*8 + 64); \
        CP_ASYNC16(sptr(_bb + B_PL + coG*272 + jG*16),       Blp + _kb + jG*8); \
        CP_ASYNC16(sptr(_bb + B_PL + coG*272 + jG*16 + 128), Blp + _kb + jG*8 + 64); \
    } while (0)

    W_ISSUE(0, 0); CP_COMMIT();

    for (int c = 0; c < WNCH; c++) {
        int s = c & 1;
        CP_WAIT0();
        __syncthreads();
        if (c + 1 < WNCH) { W_ISSUE(c + 1, s ^ 1); CP_COMMIT(); }
        uint16_t* sAh = (uint16_t*)(smem + s*STG_BYTES);
        uint16_t* sAl = (uint16_t*)(smem + s*STG_BYTES + A_PL);
        uint16_t* sBh = (uint16_t*)(smem + s*STG_BYTES + 2*A_PL);
        uint16_t* sBl = (uint16_t*)(smem + s*STG_BYTES + 2*A_PL + B_PL);
        #pragma unroll
        for (int ks = 0; ks < 4; ks++) {
            int kO = ks * 16;
            uint32_t ah[2][4], al[2][4], bh[2][4], bl[2][4];
            #pragma unroll
            for (int mt = 0; mt < 2; mt++) {
                uint32_t ad = sptr(sAh + (wco + mt*16 + (lane & 15))*SA_STR + kO + (lane >> 4)*8);
                LDSM4(ah[mt], ad);
                ad = sptr(sAl + (wco + mt*16 + (lane & 15))*SA_STR + kO + (lane >> 4)*8);
                LDSM4(al[mt], ad);
            }
            #pragma unroll
            for (int nt = 0; nt < 2; nt++) {
                uint32_t bd = sptr(sBh + (kO + (lane & 15))*SB_STR + wpx + nt*16 + (lane >> 4)*8);
                LDSM4T(bh[nt], bd);
                bd = sptr(sBl + (kO + (lane & 15))*SB_STR + wpx + nt*16 + (lane >> 4)*8);
                LDSM4T(bl[nt], bd);
            }
            #pragma unroll
            for (int mt = 0; mt < 2; mt++) {
                #pragma unroll
                for (int n8 = 0; n8 < 4; n8++) {
                    uint32_t bh0 = bh[n8 >> 1][(n8 & 1)*2], bh1 = bh[n8 >> 1][(n8 & 1)*2 + 1];
                    uint32_t bl0 = bl[n8 >> 1][(n8 & 1)*2], bl1 = bl[n8 >> 1][(n8 & 1)*2 + 1];
                    MMA16816(acc[mt][n8], ah[mt], bh0, bh1);
                    MMA16816(acc[mt][n8], ah[mt], bl0, bl1);
                    MMA16816(acc[mt][n8], al[mt], bh0, bh1);
                }
            }
        }
    }
    #undef W_ISSUE

    float* Mb = M + (size_t)zb * VSLAB;
    int r  = lane >> 2;
    int cp = (lane & 3) * 2;
    #pragma unroll
    for (int mt = 0; mt < 2; mt++) {
        #pragma unroll
        for (int hf = 0; hf < 2; hf++) {
            int co = cob + wco + mt*16 + r + hf*8;
            #pragma unroll
            for (int n8 = 0; n8 < 4; n8++) {
                int tile = tb + wpx + n8*8 + cp;
                float2 f2 = make_float2(acc[mt][n8][hf*2 + 0], acc[mt][n8][hf*2 + 1]);
                *(float2*)(Mb + (size_t)co*256 + tile) = f2;
            }
        }
    }
}

#define MODE_GELU 0
#define MODE_NONE 1
#define MODE_RELU 2

// ---------------- fused otrans, paired tiles: grid (Cc/2, NPAIR) --------------
__global__ void otrans_kernel(const float* __restrict__ M,
                              const float* __restrict__ bias,
                              const float* __restrict__ bns, const float* __restrict__ bnb,
                              float* __restrict__ f32out, int statMode,
                              float* __restrict__ stat1, float* __restrict__ stat2,
                              uint16_t* __restrict__ Vh, uint16_t* __restrict__ Vl,
                              int mode)
{
    int pair = blockIdx.y;
    int e = g_pairs[pair] & 3;
    __shared__ float s[2][SIMG];
    __shared__ float red[2][128], rm[2][128];
    int tid = threadIdx.x;
    int ch = tid >> 7, lt = tid & 127;
    int co = blockIdx.x*2 + ch;
    float* sc = s[ch];
    for (int i = lt; i < SIMG; i += 128) sc[i] = 0.f;
    __syncthreads();

    int ty = lt >> 3, txp = lt & 7;
    int t0 = ty*16 + 2*txp;
    const float* Mb = M + ((size_t)pair*NPOS*Cc + co)*256 + t0;
    float2 m2[NPOS];
    #pragma unroll
    for (int pos = 0; pos < NPOS; pos++)
        m2[pos] = *(const float2*)(Mb + (size_t)pos * VSLAB);

    float bsc = bns[e*Cc + co], bsh = bnb[e*Cc + co];
    float bi  = bias ? bias[e*Cc + co] : 0.f;

    #pragma unroll
    for (int half = 0; half < 2; half++) {
        float ta[4][6];
        #pragma unroll
        for (int c = 0; c < 6; c++) {
            float m0 = half ? m2[0*6+c].y : m2[0*6+c].x;
            float m1 = half ? m2[1*6+c].y : m2[1*6+c].x;
            float mm2 = half ? m2[2*6+c].y : m2[2*6+c].x;
            float m3 = half ? m2[3*6+c].y : m2[3*6+c].x;
            float m4 = half ? m2[4*6+c].y : m2[4*6+c].x;
            float m5 = half ? m2[5*6+c].y : m2[5*6+c].x;
            ta[0][c] = m0 + m1 + mm2 + m3 + m4;
            ta[1][c] = m1 - mm2 + 2.f*m3 - 2.f*m4;
            ta[2][c] = m1 + mm2 + 4.f*m3 + 4.f*m4;
            ta[3][c] = m1 - mm2 + 8.f*m3 - 8.f*m4 + m5;
        }
        int tx = 2*txp + half;
        #pragma unroll
        for (int i = 0; i < 4; i++) {
            float m0=ta[i][0], m1=ta[i][1], mm2=ta[i][2], m3=ta[i][3], m4=ta[i][4], m5=ta[i][5];
            float Yv[4];
            Yv[0] = m0 + m1 + mm2 + m3 + m4;
            Yv[1] = m1 - mm2 + 2.f*m3 - 2.f*m4;
            Yv[2] = m1 + mm2 + 4.f*m3 + 4.f*m4;
            Yv[3] = m1 - mm2 + 8.f*m3 - 8.f*m4 + m5;
            #pragma unroll
            for (int dx = 0; dx < 4; dx++) {
                float v = (Yv[dx] + bi) * bsc + bsh;
                if (mode == MODE_GELU)      v = gelu_tanh(v);
                else if (mode == MODE_RELU) v = fmaxf(v, 0.f);
                sc[(4*ty + i + 1)*67 + 4*tx + dx + 1] = v;
            }
        }
    }
    __syncthreads();

    if (f32out || statMode) {
        float ls = 0.f, lm = -INFINITY;
        float* oc = f32out ? f32out + ((size_t)pair*Cc + co)*HW : nullptr;
        for (int i = lt; i < HW; i += 128) {
            float v = sc[((i>>6) + 1)*67 + (i & 63) + 1];
            if (oc) oc[i] = v;
            ls += v; lm = fmaxf(lm, v);
        }
        if (statMode) {
            red[ch][lt] = ls; rm[ch][lt] = lm; __syncthreads();
            for (int k = 64; k; k >>= 1) {
                if (lt < k) { red[ch][lt] += red[ch][lt+k]; rm[ch][lt] = fmaxf(rm[ch][lt], rm[ch][lt+k]); }
                __syncthreads();
            }
            if (lt == 0) {
                stat1[pair*Cc + co] = red[ch][0] * (1.f / HW);
                if (statMode == 2) stat2[pair*Cc + co] = rm[ch][0];
            }
        }
    }
    if (Vh) {
        size_t vbase = (size_t)pair*NPOS*VSLAB + (size_t)co*256 + t0;
        tile_to_V_pair(sc, lt, vbase, Vh, Vl);
    }
}

// ---------------- fused axpy + itrans, paired: grid (Cc/2, NPAIR) -------------
__global__ void axpy_kernel(const float* __restrict__ x,
                            uint16_t* __restrict__ Vh, uint16_t* __restrict__ Vl) {
    int pair = blockIdx.y;
    int b = g_pairs[pair] >> 2;
    __shared__ float s[2][SIMG];
    int tid = threadIdx.x;
    int ch = tid >> 7, lt = tid & 127;
    int c = blockIdx.x*2 + ch;
    float* sc = s[ch];
    for (int i = lt; i < SIMG; i += 128) sc[i] = 0.f;
    __syncthreads();
    float g1 = g_g1[pair];
    const float* xc = x + ((size_t)b*Cc + c)*HW;
    const float* bc = g_bufB + ((size_t)pair*Cc + c)*HW;
    float* cc = g_bufC + ((size_t)pair*Cc + c)*HW;
    for (int i = lt; i < HW; i += 128) {
        float v = xc[i] + g1 * bc[i];
        cc[i] = v;
        sc[((i>>6) + 1)*67 + (i & 63) + 1] = v;
    }
    __syncthreads();
    int t0 = (lt >> 3)*16 + 2*(lt & 7);
    size_t vbase = (size_t)pair*NPOS*VSLAB + (size_t)c*256 + t0;
    tile_to_V_pair(sc, lt, vbase, Vh, Vl);
}

__global__ void stats_kernel(const float* __restrict__ in,
                             float* __restrict__ avg, float* __restrict__ mx) {
    int bc = blockIdx.x;
    const float* p = in + (size_t)bc * HW;
    float s = 0.f, m = -INFINITY;
    for (int i = threadIdx.x; i < HW; i += 256) {
        float v = p[i];
        s += v; m = fmaxf(m, v);
    }
    __shared__ float ss[256], sm[256];
    int t = threadIdx.x;
    ss[t] = s; sm[t] = m; __syncthreads();
    for (int k = 128; k; k >>= 1) {
        if (t < k) { ss[t] += ss[t+k]; sm[t] = fmaxf(sm[t], sm[t+k]); }
        __syncthreads();
    }
    if (t == 0) {
        avg[bc] = ss[0] * (1.f / HW);
        if (mx) mx[bc] = sm[0];
    }
}

__global__ void gate_kernel(const int* __restrict__ dom,
                            const float* __restrict__ w1, const float* __restrict__ b1,
                            const float* __restrict__ lns, const float* __restrict__ lnb,
                            const float* __restrict__ w2, const float* __restrict__ b2,
                            const float* __restrict__ dom_emb) {
    __shared__ float gi[GIN];
    __shared__ float red[256];
    __shared__ float logit[Ee];
    int t = threadIdx.x;
    for (int b = 0; b < Bz; b++) {
        for (int k = t; k < GIN; k += 256) {
            float v;
            if (k < Cc)        v = g_xavg[b*Cc + k];
            else if (k < 2*Cc) v = g_xmax[b*Cc + k - Cc];
            else               v = dom_emb[dom[b]*16 + (k - 2*Cc)];
            gi[k] = v;
        }
        __syncthreads();
        float acc = b1[t];
        for (int k = 0; k < GIN; k++) acc += gi[k] * w1[k*Cc + t];
        red[t] = acc; __syncthreads();
        for (int k = 128; k; k >>= 1) { if (t < k) red[t] += red[t+k]; __syncthreads(); }
        float mu = red[0] * (1.f / Cc);
        __syncthreads();
        red[t] = acc * acc; __syncthreads();
        for (int k = 128; k; k >>= 1) { if (t < k) red[t] += red[t+k]; __syncthreads(); }
        float var = red[0] * (1.f / Cc) - mu * mu;
        __syncthreads();
        float h = (acc - mu) * rsqrtf(var + 1e-5f) * lns[t] + lnb[t];
        h = fmaxf(h, 0.f);
        for (int e = 0; e < Ee; e++) {
            red[t] = h * w2[t*Ee + e]; __syncthreads();
            for (int k = 128; k; k >>= 1) { if (t < k) red[t] += red[t+k]; __syncthreads(); }
            if (t == 0) logit[e] = red[0] + b2[e];
            __syncthreads();
        }
        if (t == 0) {
            float mx = logit[0];
            for (int e = 1; e < Ee; e++) mx = fmaxf(mx, logit[e]);
            float pr[Ee], s = 0.f;
            for (int e = 0; e < Ee; e++) { pr[e] = __expf(logit[e] - mx); s += pr[e]; }
            for (int e = 0; e < Ee; e++) pr[e] /= s;
            int i1 = 0;
            for (int e = 1; e < Ee; e++) if (pr[e] > pr[i1]) i1 = e;
            int i2 = -1;
            for (int e = 0; e < Ee; e++) if (e != i1 && (i2 < 0 || pr[e] > pr[i2])) i2 = e;
            float s2 = pr[i1] + pr[i2];
            int lo = i1 < i2 ? i1 : i2;
            int hi = i1 < i2 ? i2 : i1;
            g_pairs[b*2 + 0] = b*4 + lo;  g_wpair[b*2 + 0] = pr[lo] / s2;
            g_pairs[b*2 + 1] = b*4 + hi;  g_wpair[b*2 + 1] = pr[hi] / s2;
        }
        __syncthreads();
    }
}

__global__ void dgate_kernel(const float* __restrict__ gw, const float* __restrict__ gb) {
    int pair = blockIdx.x;
    int e = g_pairs[pair] & 3;
    int t = threadIdx.x;
    __shared__ float red[256];
    red[t] = g_stat1[pair*Cc + t] * gw[e*Cc + t];
    __syncthreads();
    for (int k = 128; k; k >>= 1) { if (t < k) red[t] += red[t+k]; __syncthreads(); }
    if (t == 0) g_g1[pair] = sigmoidf_(red[0] + gb[e]);
}

__global__ void camlp_kernel(const float* __restrict__ w1, const float* __restrict__ w2) {
    int pair = blockIdx.x;
    int e = g_pairs[pair] & 3;
    int t = threadIdx.x;
    __shared__ float hs[CRr];
    if (t < CRr) {
        float sa_ = 0.f, sm_ = 0.f;
        const float* w1r = w1 + ((size_t)e*CRr + t) * Cc;
        for (int c = 0; c < Cc; c++) {
            sa_ += g_stat1[pair*Cc + c] * w1r[c];
            sm_ += g_stat2[pair*Cc + c] * w1r[c];
        }
        hs[t] = fmaxf(sa_, 0.f) + fmaxf(sm_, 0.f);
    }
    __syncthreads();
    float o = 0.f;
    const float* w2r = w2 + ((size_t)e*Cc + t) * CRr;
    #pragma unroll
    for (int j = 0; j < CRr; j++) o += hs[j] * w2r[j];
    g_ca[pair*Cc + t] = sigmoidf_(o);
}

__global__ void sastats_kernel() {
    int pair = blockIdx.y;
    __shared__ float sca[Cc];
    int t = threadIdx.x;
    sca[t] = g_ca[pair*Cc + t];
    __syncthreads();
    int p = blockIdx.x * 256 + t;
    float s = 0.f, m = -INFINITY;
    for (int c = 0; c < Cc; c++) {
        float v = g_bufB[((size_t)pair*Cc + c)*HW + p] * sca[c];
        s += v; m = fmaxf(m, v);
    }
    g_sain[((size_t)pair*2    )*HW + p] = s * (1.f / Cc);
    g_sain[((size_t)pair*2 + 1)*HW + p] = m;
}

__global__ void saconv_kernel(const float* __restrict__ saw) {
    int pair = blockIdx.y;
    int e = g_pairs[pair] & 3;
    __shared__ float sw[2*49];
    int t = threadIdx.x;
    if (t < 98) sw[t] = saw[e*98 + t];
    __syncthreads();
    int p = blockIdx.x * 256 + t;
    int y = p >> 6, x = p & 63;
    float a = 0.f;
    #pragma unroll
    for (int ch = 0; ch < 2; ch++)
        for (int ky = 0; ky < 7; ky++) {
            int gy = y + ky - 3;
            if (gy < 0 || gy >= Hh) continue;
            for (int kx = 0; kx < 7; kx++) {
                int gx = x + kx - 3;
                if (gx < 0 || gx >= Ww) continue;
                a += g_sain[((size_t)pair*2 + ch)*HW + gy*Ww + gx] * sw[ch*49 + ky*7 + kx];
            }
        }
    g_sa[(size_t)pair*HW + p] = sigmoidf_(a);
}

__global__ void final_kernel(const float* __restrict__ adapter, const int* __restrict__ dom,
                             float* __restrict__ out) {
    int b = blockIdx.y;
    int idx = blockIdx.x * 256 + threadIdx.x;
    int c = idx >> 12, p = idx & 4095;
    float r = 0.f;
    #pragma unroll
    for (int j = 0; j < 2; j++) {
        int pair = b*2 + j;
        int e = g_pairs[pair] & 3;
        float w = g_wpair[pair];
        size_t po = (size_t)pair * Cc * HW + idx;
        float v = g_bufB[po] * g_ca[pair*Cc + c] * g_sa[(size_t)pair*HW + p] + g_bufC[po];
        v = fmaxf(v, 0.f) + adapter[((size_t)e*Dd + dom[b])*Cc + c];
        r += w * v;
    }
    out[(size_t)b * Cc * HW + idx] = r;
}

extern "C" void kernel_launch(void* const* d_in, const int* in_sizes, int n_in,
                              void* d_out, int out_size) {
    const float* x        = (const float*)d_in[0];
    const int*   dom      = (const int*)  d_in[1];
    const float* g_w1     = (const float*)d_in[2];
    const float* g_b1     = (const float*)d_in[3];
    const float* ln_s     = (const float*)d_in[4];
    const float* ln_b     = (const float*)d_in[5];
    const float* g_w2     = (const float*)d_in[6];
    const float* g_b2     = (const float*)d_in[7];
    const float* dom_emb  = (const float*)d_in[8];
    const float* dt_w1    = (const float*)d_in[9];
    const float* dt_bn1s  = (const float*)d_in[10];
    const float* dt_bn1b  = (const float*)d_in[11];
    const float* dt_w2    = (const float*)d_in[12];
    const float* dt_bn2s  = (const float*)d_in[13];
    const float* dt_bn2b  = (const float*)d_in[14];
    const float* gate_w   = (const float*)d_in[15];
    const float* gate_b   = (const float*)d_in[16];
    const float* c1_w     = (const float*)d_in[17];
    const float* c1_b     = (const float*)d_in[18];
    const float* bn1s     = (const float*)d_in[19];
    const float* bn1b     = (const float*)d_in[20];
    const float* c2_w     = (const float*)d_in[21];
    const float* c2_b     = (const float*)d_in[22];
    const float* bn2s     = (const float*)d_in[23];
    const float* bn2b     = (const float*)d_in[24];
    const float* ca_w1    = (const float*)d_in[25];
    const float* ca_w2    = (const float*)d_in[26];
    const float* sa_w     = (const float*)d_in[27];
    const float* adapter  = (const float*)d_in[28];
    float* out = (float*)d_out;

    float *pxavg, *pxmax, *pstat1, *pstat2, *Mbuf, *bufB;
    uint16_t *Uh, *Ul, *Vh, *Vl;
    cudaGetSymbolAddress((void**)&pxavg, g_xavg);
    cudaGetSymbolAddress((void**)&pxmax, g_xmax);
    cudaGetSymbolAddress((void**)&pstat1, g_stat1);
    cudaGetSymbolAddress((void**)&pstat2, g_stat2);
    cudaGetSymbolAddress((void**)&bufB, g_bufB);
    cudaGetSymbolAddress((void**)&Uh, g_Uh);
    cudaGetSymbolAddress((void**)&Ul, g_Ul);
    cudaGetSymbolAddress((void**)&Vh, g_Vh);
    cudaGetSymbolAddress((void**)&Vl, g_Vl);
    cudaGetSymbolAddress((void**)&Mbuf, g_M);

    static int smem_set = 0;
    if (!smem_set) {
        cudaFuncSetAttribute(wgemm_kernel,
                             cudaFuncAttributeMaxDynamicSharedMemorySize, SMEM_TOTAL);
        smem_set = 1;
    }

    dim3 ggrid(2, 2, NPAIR*NPOS);
    dim3 sgrid(HW/256, NPAIR);
    dim3 fgrid(Cc*HW/256, Bz);
    dim3 wt3grid(1024, 3);
    dim3 cgP(Cc/2, NPAIR);

    prep_kernel  <<<2048, 256>>>(dt_w1, x, Uh, Ul, Vh, Vl);                          // 1
    stats_kernel <<<Bz*Cc, 256>>>(x, pxavg, pxmax);                                  // 2
    gate_kernel  <<<1, 256>>>(dom, g_w1, g_b1, ln_s, ln_b, g_w2, g_b2, dom_emb);     // 3
    wgemm_kernel <<<ggrid, 512, SMEM_TOTAL>>>(Uh, Ul, Vh, Vl, Mbuf, 1);              // 4 (ncu)
    wtrans3_kernel<<<wt3grid, 256>>>(dt_w2, c1_w, c2_w, Uh, Ul);                     // 5
    otrans_kernel<<<cgP, 256>>>(Mbuf, nullptr, dt_bn1s, dt_bn1b,
                                nullptr, 0, nullptr, nullptr, Vh, Vl, MODE_GELU);
    wgemm_kernel <<<ggrid, 512, SMEM_TOTAL>>>(Uh + (size_t)UPLANE, Ul + (size_t)UPLANE,
                                              Vh, Vl, Mbuf, 0);
    otrans_kernel<<<cgP, 256>>>(Mbuf, nullptr, dt_bn2s, dt_bn2b,
                                bufB, 1, pstat1, nullptr, nullptr, nullptr, MODE_NONE);
    dgate_kernel <<<NPAIR, 256>>>(gate_w, gate_b);
    axpy_kernel  <<<cgP, 256>>>(x, Vh, Vl);
    wgemm_kernel <<<ggrid, 512, SMEM_TOTAL>>>(Uh + 2*(size_t)UPLANE, Ul + 2*(size_t)UPLANE,
                                              Vh, Vl, Mbuf, 0);
    otrans_kernel<<<cgP, 256>>>(Mbuf, c1_b, bn1s, bn1b,
                                nullptr, 0, nullptr, nullptr, Vh, Vl, MODE_RELU);
    wgemm_kernel <<<ggrid, 512, SMEM_TOTAL>>>(Uh + 3*(size_t)UPLANE, Ul + 3*(size_t)UPLANE,
                                              Vh, Vl, Mbuf, 0);
    otrans_kernel<<<cgP, 256>>>(Mbuf, c2_b, bn2s, bn2b,
                                bufB, 2, pstat1, pstat2, nullptr, nullptr, MODE_NONE);
    camlp_kernel <<<NPAIR, 256>>>(ca_w1, ca_w2);
    sastats_kernel<<<sgrid, 256>>>();
    saconv_kernel<<<sgrid, 256>>>(sa_w);
    final_kernel <<<fgrid, 256>>>(adapter, dom, out);
}

// round 14
// speedup vs baseline: 1.0981x; 1.0981x over previous
#include <cuda_runtime.h>
#include <cuda_bf16.h>
#include <math.h>
#include <stdint.h>

#define Bz   8
#define Cc   256
#define Hh   64
#define Ww   64
#define HW   (Hh*Ww)
#define Ee   4
#define Dd   4
#define CRr  16
#define GIN  (2*Cc+16)
#define NPAIR 16

#define NTIL   256
#define NPOS   36
#define VSLAB  (Cc*NTIL)
#define USLAB  (Cc*Cc)
#define UPLANE (Ee*NPOS*USLAB)
#define WKT    256
#define WKCH   32
#define WNCH   (WKT/WKCH)     // 8
#define SIMG   (66*67)

// smem strides (u16 units) for KCH=32 stages
#define SA_STR 40             // 32 k + 8 pad -> 80B rows
#define SB_STR 136            // 128 n + 8 pad -> 272B rows
#define A_PL   (128*SA_STR*2)         // 10240 B
#define B_PL   (32*SB_STR*2)          // 8704 B
#define STG_BYTES (2*A_PL + 2*B_PL)   // 37888
#define SMEM_TOTAL (2*STG_BYTES)      // 75776  -> 2 CTAs/SM

__device__ float    g_bufB[NPAIR*Cc*HW];
__device__ float    g_bufC[NPAIR*Cc*HW];
__device__ __align__(16) uint16_t g_Uh[4*UPLANE];
__device__ __align__(16) uint16_t g_Ul[4*UPLANE];
__device__ __align__(16) uint16_t g_Vh[NPAIR*NPOS*VSLAB];
__device__ __align__(16) uint16_t g_Vl[NPAIR*NPOS*VSLAB];
__device__ float    g_M [NPAIR*NPOS*VSLAB];
__device__ float g_xavg[Bz*Cc];
__device__ float g_xmax[Bz*Cc];
__device__ float g_stat1[NPAIR*Cc];
__device__ float g_stat2[NPAIR*Cc];
__device__ int   g_pairs[NPAIR];
__device__ float g_wpair[NPAIR];
__device__ float g_g1[NPAIR];
__device__ float g_ca[NPAIR*Cc];
__device__ float g_sain[NPAIR*2*HW];
__device__ float g_sa[NPAIR*HW];

__device__ __forceinline__ float sigmoidf_(float x) { return 1.f / (1.f + __expf(-x)); }
__device__ __forceinline__ float gelu_tanh(float v) {
    float x3 = v * v * v;
    return 0.5f * v * (1.f + tanhf(0.7978845608028654f * (v + 0.044715f * x3)));
}
__device__ __forceinline__ void split_hilo(float v, uint16_t& h, uint16_t& l) {
    __nv_bfloat16 hb = __float2bfloat16(v);
    float r = v - __bfloat162float(hb);
    h = __bfloat16_as_ushort(hb);
    l = __bfloat16_as_ushort(__float2bfloat16(r));
}
__device__ __forceinline__ uint32_t sptr(const void* p) {
    return (uint32_t)__cvta_generic_to_shared(p);
}

#define CP_ASYNC16(dst, src) \
    asm volatile("cp.async.cg.shared.global [%0], [%1], 16;" :: "r"(dst), "l"(src))
#define CP_COMMIT() asm volatile("cp.async.commit_group;" ::: "memory")
#define CP_WAIT0()  asm volatile("cp.async.wait_group 0;" ::: "memory")

#define LDSM4(r, addr) \
    asm volatile("ldmatrix.sync.aligned.m8n8.x4.shared.b16 {%0,%1,%2,%3}, [%4];" \
        : "=r"((r)[0]), "=r"((r)[1]), "=r"((r)[2]), "=r"((r)[3]) : "r"(addr))
#define LDSM4T(r, addr) \
    asm volatile("ldmatrix.sync.aligned.m8n8.x4.trans.shared.b16 {%0,%1,%2,%3}, [%4];" \
        : "=r"((r)[0]), "=r"((r)[1]), "=r"((r)[2]), "=r"((r)[3]) : "r"(addr))
#define MMA16816(d, a, b0_, b1_) \
    asm volatile("mma.sync.aligned.m16n8k16.row.col.f32.bf16.bf16.f32 " \
        "{%0,%1,%2,%3}, {%4,%5,%6,%7}, {%8,%9}, {%0,%1,%2,%3};" \
        : "+f"((d)[0]), "+f"((d)[1]), "+f"((d)[2]), "+f"((d)[3]) \
        : "r"((a)[0]), "r"((a)[1]), "r"((a)[2]), "r"((a)[3]), "r"(b0_), "r"(b1_))

// ---------------- paired tile input transform --------------------------------
__device__ __forceinline__ void tile_to_V_pair(const float* s, int p, size_t vbase0,
                                               uint16_t* __restrict__ Vh,
                                               uint16_t* __restrict__ Vl) {
    int ty = p >> 3, txp = p & 7;
    const float* sp = s + (4*ty)*67 + 8*txp;
    float w[6][10];
    #pragma unroll
    for (int c = 0; c < 10; c++) {
        float d0=sp[0*67+c], d1=sp[1*67+c], d2=sp[2*67+c],
              d3=sp[3*67+c], d4=sp[4*67+c], d5=sp[5*67+c];
        w[0][c] = 4.f*d0 - 5.f*d2 + d4;
        w[1][c] = -4.f*d1 - 4.f*d2 + d3 + d4;
        w[2][c] =  4.f*d1 - 4.f*d2 - d3 + d4;
        w[3][c] = -2.f*d1 - d2 + 2.f*d3 + d4;
        w[4][c] =  2.f*d1 - d2 - 2.f*d3 + d4;
        w[5][c] =  4.f*d1 - 5.f*d3 + d5;
    }
    #pragma unroll
    for (int r = 0; r < 6; r++) {
        float v0[6], v1[6];
        {
            float d0=w[r][0], d1=w[r][1], d2=w[r][2], d3=w[r][3], d4=w[r][4], d5=w[r][5];
            v0[0] = 4.f*d0 - 5.f*d2 + d4;
            v0[1] = -4.f*d1 - 4.f*d2 + d3 + d4;
            v0[2] =  4.f*d1 - 4.f*d2 - d3 + d4;
            v0[3] = -2.f*d1 - d2 + 2.f*d3 + d4;
            v0[4] =  2.f*d1 - d2 - 2.f*d3 + d4;
            v0[5] =  4.f*d1 - 5.f*d3 + d5;
        }
        {
            float d0=w[r][4], d1=w[r][5], d2=w[r][6], d3=w[r][7], d4=w[r][8], d5=w[r][9];
            v1[0] = 4.f*d0 - 5.f*d2 + d4;
            v1[1] = -4.f*d1 - 4.f*d2 + d3 + d4;
            v1[2] =  4.f*d1 - 4.f*d2 - d3 + d4;
            v1[3] = -2.f*d1 - d2 + 2.f*d3 + d4;
            v1[4] =  2.f*d1 - d2 - 2.f*d3 + d4;
            v1[5] =  4.f*d1 - 5.f*d3 + d5;
        }
        #pragma unroll
        for (int c = 0; c < 6; c++) {
            uint16_t h0, l0, h1, l1;
            split_hilo(v0[c], h0, l0);
            split_hilo(v1[c], h1, l1);
            size_t o = vbase0 + (size_t)(r*6 + c) * VSLAB;
            *(uint32_t*)(Vh + o) = (uint32_t)h0 | ((uint32_t)h1 << 16);
            *(uint32_t*)(Vl + o) = (uint32_t)l0 | ((uint32_t)l1 << 16);
        }
    }
}

__device__ __forceinline__ void wtrans_body(const float* __restrict__ w, int idx,
                                            uint16_t* __restrict__ Uh,
                                            uint16_t* __restrict__ Ul) {
    int ci = idx & 255, co = (idx >> 8) & 255, e = idx >> 16;
    const float* g = w + (size_t)idx * 9;
    float q[3][3];
    #pragma unroll
    for (int i = 0; i < 3; i++)
        #pragma unroll
        for (int j = 0; j < 3; j++) q[i][j] = g[i*3 + j];
    const float S6 = 1.f/6.f, S24 = 1.f/24.f;
    float t[6][3];
    #pragma unroll
    for (int c = 0; c < 3; c++) {
        float a = q[0][c], b = q[1][c], d = q[2][c];
        t[0][c] = 0.25f * a;
        t[1][c] = -S6 * (a + b + d);
        t[2][c] = -S6 * (a - b + d);
        t[3][c] = S24 * (a + 2.f*b + 4.f*d);
        t[4][c] = S24 * (a - 2.f*b + 4.f*d);
        t[5][c] = d;
    }
    #pragma unroll
    for (int r = 0; r < 6; r++) {
        float a = t[r][0], b = t[r][1], d = t[r][2];
        float uu[6];
        uu[0] = 0.25f * a;
        uu[1] = -S6 * (a + b + d);
        uu[2] = -S6 * (a - b + d);
        uu[3] = S24 * (a + 2.f*b + 4.f*d);
        uu[4] = S24 * (a - 2.f*b + 4.f*d);
        uu[5] = d;
        #pragma unroll
        for (int c = 0; c < 6; c++) {
            uint16_t hh, ll; split_hilo(uu[c], hh, ll);
            size_t o = ((size_t)(e*NPOS + r*6 + c) * Cc + co) * 256 + ci;
            Uh[o] = hh; Ul[o] = ll;
        }
    }
}

// prep: conv1 wtrans (blocks 0..1023) + itransx (1024..2047)
__global__ void prep_kernel(const float* __restrict__ w1, const float* __restrict__ x,
                            uint16_t* __restrict__ Uh, uint16_t* __restrict__ Ul,
                            uint16_t* __restrict__ Vh, uint16_t* __restrict__ Vl) {
    __shared__ float s[2][SIMG];
    int tid = threadIdx.x;
    if (blockIdx.x < 1024) {
        wtrans_body(w1, blockIdx.x * 256 + tid, Uh, Ul);
        return;
    }
    int bi = blockIdx.x - 1024;
    int c2 = bi & 127, b = bi >> 7;
    int ch = tid >> 7, lt = tid & 127;
    int c = c2*2 + ch;
    float* sc = s[ch];
    for (int i = lt; i < SIMG; i += 128) sc[i] = 0.f;
    __syncthreads();
    const float* xc = x + ((size_t)b*Cc + c)*HW;
    for (int i = lt; i < HW; i += 128)
        sc[((i>>6) + 1)*67 + (i & 63) + 1] = xc[i];
    __syncthreads();
    int t0 = (lt >> 3)*16 + 2*(lt & 7);
    size_t vbase = (size_t)b*NPOS*VSLAB + (size_t)c*256 + t0;
    tile_to_V_pair(sc, lt, vbase, Vh, Vl);
}

__global__ void wtrans3_kernel(const float* __restrict__ wa, const float* __restrict__ wb,
                               const float* __restrict__ wc,
                               uint16_t* __restrict__ Uh, uint16_t* __restrict__ Ul) {
    int cv = blockIdx.y;
    const float* w = (cv == 0) ? wa : (cv == 1) ? wb : wc;
    wtrans_body(w, blockIdx.x * 256 + threadIdx.x,
                Uh + (size_t)(cv + 1)*UPLANE, Ul + (size_t)(cv + 1)*UPLANE);
}

// ---------------- Winograd GEMM: 256 thr, 2 CTAs/SM ---------------------------
__global__ __launch_bounds__(256, 2) void wgemm_kernel(
    const uint16_t* __restrict__ Uh, const uint16_t* __restrict__ Ul,
    const uint16_t* __restrict__ Vh, const uint16_t* __restrict__ Vl,
    float* __restrict__ M, int vByBatch)
{
    int zb = blockIdx.z;
    int pair = zb / NPOS, pos = zb - pair*NPOS;
    int pe = g_pairs[pair];
    int e = pe & 3;
    int vslot = vByBatch ? (pe >> 2) : pair;
    int cob = blockIdx.y * 128;
    int tb  = blockIdx.x * 128;

    const uint16_t* Ahp = Uh + ((size_t)(e*NPOS + pos) * Cc + cob) * 256;
    const uint16_t* Alp = Ul + ((size_t)(e*NPOS + pos) * Cc + cob) * 256;
    const uint16_t* Bhp = Vh + (size_t)(vslot*NPOS + pos) * VSLAB + tb;
    const uint16_t* Blp = Vl + (size_t)(vslot*NPOS + pos) * VSLAB + tb;

    extern __shared__ __align__(16) char smem[];
    int tid  = threadIdx.x;
    int lane = tid & 31, wid = tid >> 5;   // 8 warps
    int wco  = (wid & 3) * 32;             // 4 co groups
    int wpx  = (wid >> 2) * 64;            // 2 px groups

    // A fill roles: 64B rows, 4 granules; coG 0..63, jG 0..3
    int coG = tid >> 2, jG = tid & 3;
    // B fill roles: 272B-stride rows of 256B data = 16 granules; kB2 0..31, jB 0..7
    int kB2 = tid >> 3, jB = tid & 7;

    float acc[2][8][4];
    #pragma unroll
    for (int mt = 0; mt < 2; mt++)
        #pragma unroll
        for (int nt = 0; nt < 8; nt++)
            #pragma unroll
            for (int q = 0; q < 4; q++) acc[mt][nt][q] = 0.f;

    #define W_ISSUE(c, s) do { \
        char* _ab = smem + (s)*STG_BYTES; \
        size_t _ka = (size_t)(c) * WKCH + jG*8; \
        CP_ASYNC16(sptr(_ab + coG*80 + jG*16),             Ahp + (size_t)coG*256 + _ka); \
        CP_ASYNC16(sptr(_ab + (coG+64)*80 + jG*16),        Ahp + (size_t)(coG+64)*256 + _ka); \
        CP_ASYNC16(sptr(_ab + A_PL + coG*80 + jG*16),      Alp + (size_t)coG*256 + _ka); \
        CP_ASYNC16(sptr(_ab + A_PL + (coG+64)*80 + jG*16), Alp + (size_t)(coG+64)*256 + _ka); \
        char* _bb = _ab + 2*A_PL; \
        size_t _kb = (size_t)((c)*WKCH + kB2) * 256; \
        CP_ASYNC16(sptr(_bb + kB2*272 + jB*16),         Bhp + _kb + jB*8); \
        CP_ASYNC16(sptr(_bb + kB2*272 + jB*16 + 128),   Bhp + _kb + jB*8 + 64); \
        CP_ASYNC16(sptr(_bb + B_PL + kB2*272 + jB*16),       Blp + _kb + jB*8); \
        CP_ASYNC16(sptr(_bb + B_PL + kB2*272 + jB*16 + 128), Blp + _kb + jB*8 + 64); \
    } while (0)

    W_ISSUE(0, 0); CP_COMMIT();

    for (int c = 0; c < WNCH; c++) {
        int s = c & 1;
        CP_WAIT0();
        __syncthreads();
        if (c + 1 < WNCH) { W_ISSUE(c + 1, s ^ 1); CP_COMMIT(); }
        uint16_t* sAh = (uint16_t*)(smem + s*STG_BYTES);
        uint16_t* sAl = (uint16_t*)(smem + s*STG_BYTES + A_PL);
        uint16_t* sBh = (uint16_t*)(smem + s*STG_BYTES + 2*A_PL);
        uint16_t* sBl = (uint16_t*)(smem + s*STG_BYTES + 2*A_PL + B_PL);
        #pragma unroll
        for (int ks = 0; ks < 2; ks++) {
            int kO = ks * 16;
            uint32_t ah[2][4], al[2][4], bh[4][4], bl[4][4];
            #pragma unroll
            for (int mt = 0; mt < 2; mt++) {
                uint32_t ad = sptr(sAh + (wco + mt*16 + (lane & 15))*SA_STR + kO + (lane >> 4)*8);
                LDSM4(ah[mt], ad);
                ad = sptr(sAl + (wco + mt*16 + (lane & 15))*SA_STR + kO + (lane >> 4)*8);
                LDSM4(al[mt], ad);
            }
            #pragma unroll
            for (int nt = 0; nt < 4; nt++) {
                uint32_t bd = sptr(sBh + (kO + (lane & 15))*SB_STR + wpx + nt*16 + (lane >> 4)*8);
                LDSM4T(bh[nt], bd);
                bd = sptr(sBl + (kO + (lane & 15))*SB_STR + wpx + nt*16 + (lane >> 4)*8);
                LDSM4T(bl[nt], bd);
            }
            #pragma unroll
            for (int mt = 0; mt < 2; mt++) {
                #pragma unroll
                for (int n8 = 0; n8 < 8; n8++) {
                    uint32_t bh0 = bh[n8 >> 1][(n8 & 1)*2], bh1 = bh[n8 >> 1][(n8 & 1)*2 + 1];
                    uint32_t bl0 = bl[n8 >> 1][(n8 & 1)*2], bl1 = bl[n8 >> 1][(n8 & 1)*2 + 1];
                    MMA16816(acc[mt][n8], ah[mt], bh0, bh1);
                    MMA16816(acc[mt][n8], ah[mt], bl0, bl1);
                    MMA16816(acc[mt][n8], al[mt], bh0, bh1);
                }
            }
        }
    }
    #undef W_ISSUE

    float* Mb = M + (size_t)zb * VSLAB;
    int r  = lane >> 2;
    int cp = (lane & 3) * 2;
    #pragma unroll
    for (int mt = 0; mt < 2; mt++) {
        #pragma unroll
        for (int hf = 0; hf < 2; hf++) {
            int co = cob + wco + mt*16 + r + hf*8;
            #pragma unroll
            for (int n8 = 0; n8 < 8; n8++) {
                int tile = tb + wpx + n8*8 + cp;
                float2 f2 = make_float2(acc[mt][n8][hf*2 + 0], acc[mt][n8][hf*2 + 1]);
                *(float2*)(Mb + (size_t)co*256 + tile) = f2;
            }
        }
    }
}

#define MODE_GELU 0
#define MODE_NONE 1
#define MODE_RELU 2

// fused otrans, paired tiles: grid (Cc/2, NPAIR)
__global__ void otrans_kernel(const float* __restrict__ M,
                              const float* __restrict__ bias,
                              const float* __restrict__ bns, const float* __restrict__ bnb,
                              float* __restrict__ f32out, int statMode,
                              float* __restrict__ stat1, float* __restrict__ stat2,
                              uint16_t* __restrict__ Vh, uint16_t* __restrict__ Vl,
                              int mode)
{
    int pair = blockIdx.y;
    int e = g_pairs[pair] & 3;
    __shared__ float s[2][SIMG];
    __shared__ float red[2][128], rm[2][128];
    int tid = threadIdx.x;
    int ch = tid >> 7, lt = tid & 127;
    int co = blockIdx.x*2 + ch;
    float* sc = s[ch];
    for (int i = lt; i < SIMG; i += 128) sc[i] = 0.f;
    __syncthreads();

    int ty = lt >> 3, txp = lt & 7;
    int t0 = ty*16 + 2*txp;
    const float* Mb = M + ((size_t)pair*NPOS*Cc + co)*256 + t0;
    float2 m2[NPOS];
    #pragma unroll
    for (int pos = 0; pos < NPOS; pos++)
        m2[pos] = *(const float2*)(Mb + (size_t)pos * VSLAB);

    float bsc = bns[e*Cc + co], bsh = bnb[e*Cc + co];
    float bi  = bias ? bias[e*Cc + co] : 0.f;

    #pragma unroll
    for (int half = 0; half < 2; half++) {
        float ta[4][6];
        #pragma unroll
        for (int c = 0; c < 6; c++) {
            float m0 = half ? m2[0*6+c].y : m2[0*6+c].x;
            float m1 = half ? m2[1*6+c].y : m2[1*6+c].x;
            float mm2 = half ? m2[2*6+c].y : m2[2*6+c].x;
            float m3 = half ? m2[3*6+c].y : m2[3*6+c].x;
            float m4 = half ? m2[4*6+c].y : m2[4*6+c].x;
            float m5 = half ? m2[5*6+c].y : m2[5*6+c].x;
            ta[0][c] = m0 + m1 + mm2 + m3 + m4;
            ta[1][c] = m1 - mm2 + 2.f*m3 - 2.f*m4;
            ta[2][c] = m1 + mm2 + 4.f*m3 + 4.f*m4;
            ta[3][c] = m1 - mm2 + 8.f*m3 - 8.f*m4 + m5;
        }
        int tx = 2*txp + half;
        #pragma unroll
        for (int i = 0; i < 4; i++) {
            float m0=ta[i][0], m1=ta[i][1], mm2=ta[i][2], m3=ta[i][3], m4=ta[i][4], m5=ta[i][5];
            float Yv[4];
            Yv[0] = m0 + m1 + mm2 + m3 + m4;
            Yv[1] = m1 - mm2 + 2.f*m3 - 2.f*m4;
            Yv[2] = m1 + mm2 + 4.f*m3 + 4.f*m4;
            Yv[3] = m1 - mm2 + 8.f*m3 - 8.f*m4 + m5;
            #pragma unroll
            for (int dx = 0; dx < 4; dx++) {
                float v = (Yv[dx] + bi) * bsc + bsh;
                if (mode == MODE_GELU)      v = gelu_tanh(v);
                else if (mode == MODE_RELU) v = fmaxf(v, 0.f);
                sc[(4*ty + i + 1)*67 + 4*tx + dx + 1] = v;
            }
        }
    }
    __syncthreads();

    if (f32out || statMode) {
        float ls = 0.f, lm = -INFINITY;
        float* oc = f32out ? f32out + ((size_t)pair*Cc + co)*HW : nullptr;
        for (int i = lt; i < HW; i += 128) {
            float v = sc[((i>>6) + 1)*67 + (i & 63) + 1];
            if (oc) oc[i] = v;
            ls += v; lm = fmaxf(lm, v);
        }
        if (statMode) {
            red[ch][lt] = ls; rm[ch][lt] = lm; __syncthreads();
            for (int k = 64; k; k >>= 1) {
                if (lt < k) { red[ch][lt] += red[ch][lt+k]; rm[ch][lt] = fmaxf(rm[ch][lt], rm[ch][lt+k]); }
                __syncthreads();
            }
            if (lt == 0) {
                stat1[pair*Cc + co] = red[ch][0] * (1.f / HW);
                if (statMode == 2) stat2[pair*Cc + co] = rm[ch][0];
            }
        }
    }
    if (Vh) {
        size_t vbase = (size_t)pair*NPOS*VSLAB + (size_t)co*256 + t0;
        tile_to_V_pair(sc, lt, vbase, Vh, Vl);
    }
}

// fused axpy + itrans, paired: grid (Cc/2, NPAIR)
__global__ void axpy_kernel(const float* __restrict__ x,
                            uint16_t* __restrict__ Vh, uint16_t* __restrict__ Vl) {
    int pair = blockIdx.y;
    int b = g_pairs[pair] >> 2;
    __shared__ float s[2][SIMG];
    int tid = threadIdx.x;
    int ch = tid >> 7, lt = tid & 127;
    int c = blockIdx.x*2 + ch;
    float* sc = s[ch];
    for (int i = lt; i < SIMG; i += 128) sc[i] = 0.f;
    __syncthreads();
    float g1 = g_g1[pair];
    const float* xc = x + ((size_t)b*Cc + c)*HW;
    const float* bc = g_bufB + ((size_t)pair*Cc + c)*HW;
    float* cc = g_bufC + ((size_t)pair*Cc + c)*HW;
    for (int i = lt; i < HW; i += 128) {
        float v = xc[i] + g1 * bc[i];
        cc[i] = v;
        sc[((i>>6) + 1)*67 + (i & 63) + 1] = v;
    }
    __syncthreads();
    int t0 = (lt >> 3)*16 + 2*(lt & 7);
    size_t vbase = (size_t)pair*NPOS*VSLAB + (size_t)c*256 + t0;
    tile_to_V_pair(sc, lt, vbase, Vh, Vl);
}

__global__ void stats_kernel(const float* __restrict__ in,
                             float* __restrict__ avg, float* __restrict__ mx) {
    int bc = blockIdx.x;
    const float* p = in + (size_t)bc * HW;
    float s = 0.f, m = -INFINITY;
    for (int i = threadIdx.x; i < HW; i += 256) {
        float v = p[i];
        s += v; m = fmaxf(m, v);
    }
    __shared__ float ss[256], sm[256];
    int t = threadIdx.x;
    ss[t] = s; sm[t] = m; __syncthreads();
    for (int k = 128; k; k >>= 1) {
        if (t < k) { ss[t] += ss[t+k]; sm[t] = fmaxf(sm[t], sm[t+k]); }
        __syncthreads();
    }
    if (t == 0) {
        avg[bc] = ss[0] * (1.f / HW);
        if (mx) mx[bc] = sm[0];
    }
}

__global__ void gate_kernel(const int* __restrict__ dom,
                            const float* __restrict__ w1, const float* __restrict__ b1,
                            const float* __restrict__ lns, const float* __restrict__ lnb,
                            const float* __restrict__ w2, const float* __restrict__ b2,
                            const float* __restrict__ dom_emb) {
    __shared__ float gi[GIN];
    __shared__ float red[256];
    __shared__ float logit[Ee];
    int t = threadIdx.x;
    for (int b = 0; b < Bz; b++) {
        for (int k = t; k < GIN; k += 256) {
            float v;
            if (k < Cc)        v = g_xavg[b*Cc + k];
            else if (k < 2*Cc) v = g_xmax[b*Cc + k - Cc];
            else               v = dom_emb[dom[b]*16 + (k - 2*Cc)];
            gi[k] = v;
        }
        __syncthreads();
        float acc = b1[t];
        for (int k = 0; k < GIN; k++) acc += gi[k] * w1[k*Cc + t];
        red[t] = acc; __syncthreads();
        for (int k = 128; k; k >>= 1) { if (t < k) red[t] += red[t+k]; __syncthreads(); }
        float mu = red[0] * (1.f / Cc);
        __syncthreads();
        red[t] = acc * acc; __syncthreads();
        for (int k = 128; k; k >>= 1) { if (t < k) red[t] += red[t+k]; __syncthreads(); }
        float var = red[0] * (1.f / Cc) - mu * mu;
        __syncthreads();
        float h = (acc - mu) * rsqrtf(var + 1e-5f) * lns[t] + lnb[t];
        h = fmaxf(h, 0.f);
        for (int e = 0; e < Ee; e++) {
            red[t] = h * w2[t*Ee + e]; __syncthreads();
            for (int k = 128; k; k >>= 1) { if (t < k) red[t] += red[t+k]; __syncthreads(); }
            if (t == 0) logit[e] = red[0] + b2[e];
            __syncthreads();
        }
        if (t == 0) {
            float mx = logit[0];
            for (int e = 1; e < Ee; e++) mx = fmaxf(mx, logit[e]);
            float pr[Ee], s = 0.f;
            for (int e = 0; e < Ee; e++) { pr[e] = __expf(logit[e] - mx); s += pr[e]; }
            for (int e = 0; e < Ee; e++) pr[e] /= s;
            int i1 = 0;
            for (int e = 1; e < Ee; e++) if (pr[e] > pr[i1]) i1 = e;
            int i2 = -1;
            for (int e = 0; e < Ee; e++) if (e != i1 && (i2 < 0 || pr[e] > pr[i2])) i2 = e;
            float s2 = pr[i1] + pr[i2];
            int lo = i1 < i2 ? i1 : i2;
            int hi = i1 < i2 ? i2 : i1;
            g_pairs[b*2 + 0] = b*4 + lo;  g_wpair[b*2 + 0] = pr[lo] / s2;
            g_pairs[b*2 + 1] = b*4 + hi;  g_wpair[b*2 + 1] = pr[hi] / s2;
        }
        __syncthreads();
    }
}

__global__ void dgate_kernel(const float* __restrict__ gw, const float* __restrict__ gb) {
    int pair = blockIdx.x;
    int e = g_pairs[pair] & 3;
    int t = threadIdx.x;
    __shared__ float red[256];
    red[t] = g_stat1[pair*Cc + t] * gw[e*Cc + t];
    __syncthreads();
    for (int k = 128; k; k >>= 1) { if (t < k) red[t] += red[t+k]; __syncthreads(); }
    if (t == 0) g_g1[pair] = sigmoidf_(red[0] + gb[e]);
}

__global__ void camlp_kernel(const float* __restrict__ w1, const float* __restrict__ w2) {
    int pair = blockIdx.x;
    int e = g_pairs[pair] & 3;
    int t = threadIdx.x;
    __shared__ float hs[CRr];
    if (t < CRr) {
        float sa_ = 0.f, sm_ = 0.f;
        const float* w1r = w1 + ((size_t)e*CRr + t) * Cc;
        for (int c = 0; c < Cc; c++) {
            sa_ += g_stat1[pair*Cc + c] * w1r[c];
            sm_ += g_stat2[pair*Cc + c] * w1r[c];
        }
        hs[t] = fmaxf(sa_, 0.f) + fmaxf(sm_, 0.f);
    }
    __syncthreads();
    float o = 0.f;
    const float* w2r = w2 + ((size_t)e*Cc + t) * CRr;
    #pragma unroll
    for (int j = 0; j < CRr; j++) o += hs[j] * w2r[j];
    g_ca[pair*Cc + t] = sigmoidf_(o);
}

__global__ void sastats_kernel() {
    int pair = blockIdx.y;
    __shared__ float sca[Cc];
    int t = threadIdx.x;
    sca[t] = g_ca[pair*Cc + t];
    __syncthreads();
    int p = blockIdx.x * 256 + t;
    float s = 0.f, m = -INFINITY;
    for (int c = 0; c < Cc; c++) {
        float v = g_bufB[((size_t)pair*Cc + c)*HW + p] * sca[c];
        s += v; m = fmaxf(m, v);
    }
    g_sain[((size_t)pair*2    )*HW + p] = s * (1.f / Cc);
    g_sain[((size_t)pair*2 + 1)*HW + p] = m;
}

__global__ void saconv_kernel(const float* __restrict__ saw) {
    int pair = blockIdx.y;
    int e = g_pairs[pair] & 3;
    __shared__ float sw[2*49];
    int t = threadIdx.x;
    if (t < 98) sw[t] = saw[e*98 + t];
    __syncthreads();
    int p = blockIdx.x * 256 + t;
    int y = p >> 6, x = p & 63;
    float a = 0.f;
    #pragma unroll
    for (int ch = 0; ch < 2; ch++)
        for (int ky = 0; ky < 7; ky++) {
            int gy = y + ky - 3;
            if (gy < 0 || gy >= Hh) continue;
            for (int kx = 0; kx < 7; kx++) {
                int gx = x + kx - 3;
                if (gx < 0 || gx >= Ww) continue;
                a += g_sain[((size_t)pair*2 + ch)*HW + gy*Ww + gx] * sw[ch*49 + ky*7 + kx];
            }
        }
    g_sa[(size_t)pair*HW + p] = sigmoidf_(a);
}

__global__ void final_kernel(const float* __restrict__ adapter, const int* __restrict__ dom,
                             float* __restrict__ out) {
    int b = blockIdx.y;
    int idx = blockIdx.x * 256 + threadIdx.x;
    int c = idx >> 12, p = idx & 4095;
    float r = 0.f;
    #pragma unroll
    for (int j = 0; j < 2; j++) {
        int pair = b*2 + j;
        int e = g_pairs[pair] & 3;
        float w = g_wpair[pair];
        size_t po = (size_t)pair * Cc * HW + idx;
        float v = g_bufB[po] * g_ca[pair*Cc + c] * g_sa[(size_t)pair*HW + p] + g_bufC[po];
        v = fmaxf(v, 0.f) + adapter[((size_t)e*Dd + dom[b])*Cc + c];
        r += w * v;
    }
    out[(size_t)b * Cc * HW + idx] = r;
}

extern "C" void kernel_launch(void* const* d_in, const int* in_sizes, int n_in,
                              void* d_out, int out_size) {
    const float* x        = (const float*)d_in[0];
    const int*   dom      = (const int*)  d_in[1];
    const float* g_w1     = (const float*)d_in[2];
    const float* g_b1     = (const float*)d_in[3];
    const float* ln_s     = (const float*)d_in[4];
    const float* ln_b     = (const float*)d_in[5];
    const float* g_w2     = (const float*)d_in[6];
    const float* g_b2     = (const float*)d_in[7];
    const float* dom_emb  = (const float*)d_in[8];
    const float* dt_w1    = (const float*)d_in[9];
    const float* dt_bn1s  = (const float*)d_in[10];
    const float* dt_bn1b  = (const float*)d_in[11];
    const float* dt_w2    = (const float*)d_in[12];
    const float* dt_bn2s  = (const float*)d_in[13];
    const float* dt_bn2b  = (const float*)d_in[14];
    const float* gate_w   = (const float*)d_in[15];
    const float* gate_b   = (const float*)d_in[16];
    const float* c1_w     = (const float*)d_in[17];
    const float* c1_b     = (const float*)d_in[18];
    const float* bn1s     = (const float*)d_in[19];
    const float* bn1b     = (const float*)d_in[20];
    const float* c2_w     = (const float*)d_in[21];
    const float* c2_b     = (const float*)d_in[22];
    const float* bn2s     = (const float*)d_in[23];
    const float* bn2b     = (const float*)d_in[24];
    const float* ca_w1    = (const float*)d_in[25];
    const float* ca_w2    = (const float*)d_in[26];
    const float* sa_w     = (const float*)d_in[27];
    const float* adapter  = (const float*)d_in[28];
    float* out = (float*)d_out;

    float *pxavg, *pxmax, *pstat1, *pstat2, *Mbuf, *bufB;
    uint16_t *Uh, *Ul, *Vh, *Vl;
    cudaGetSymbolAddress((void**)&pxavg, g_xavg);
    cudaGetSymbolAddress((void**)&pxmax, g_xmax);
    cudaGetSymbolAddress((void**)&pstat1, g_stat1);
    cudaGetSymbolAddress((void**)&pstat2, g_stat2);
    cudaGetSymbolAddress((void**)&bufB, g_bufB);
    cudaGetSymbolAddress((void**)&Uh, g_Uh);
    cudaGetSymbolAddress((void**)&Ul, g_Ul);
    cudaGetSymbolAddress((void**)&Vh, g_Vh);
    cudaGetSymbolAddress((void**)&Vl, g_Vl);
    cudaGetSymbolAddress((void**)&Mbuf, g_M);

    static int smem_set = 0;
    if (!smem_set) {
        cudaFuncSetAttribute(wgemm_kernel,
                             cudaFuncAttributeMaxDynamicSharedMemorySize, SMEM_TOTAL);
        smem_set = 1;
    }

    dim3 ggrid(2, 2, NPAIR*NPOS);
    dim3 sgrid(HW/256, NPAIR);
    dim3 fgrid(Cc*HW/256, Bz);
    dim3 wt3grid(1024, 3);
    dim3 cgP(Cc/2, NPAIR);

    prep_kernel  <<<2048, 256>>>(dt_w1, x, Uh, Ul, Vh, Vl);                          // 1
    stats_kernel <<<Bz*Cc, 256>>>(x, pxavg, pxmax);                                  // 2
    gate_kernel  <<<1, 256>>>(dom, g_w1, g_b1, ln_s, ln_b, g_w2, g_b2, dom_emb);     // 3
    wgemm_kernel <<<ggrid, 256, SMEM_TOTAL>>>(Uh, Ul, Vh, Vl, Mbuf, 1);              // 4 (ncu)
    wtrans3_kernel<<<wt3grid, 256>>>(dt_w2, c1_w, c2_w, Uh, Ul);                     // 5
    otrans_kernel<<<cgP, 256>>>(Mbuf, nullptr, dt_bn1s, dt_bn1b,
                                nullptr, 0, nullptr, nullptr, Vh, Vl, MODE_GELU);
    wgemm_kernel <<<ggrid, 256, SMEM_TOTAL>>>(Uh + (size_t)UPLANE, Ul + (size_t)UPLANE,
                                              Vh, Vl, Mbuf, 0);
    otrans_kernel<<<cgP, 256>>>(Mbuf, nullptr, dt_bn2s, dt_bn2b,
                                bufB, 1, pstat1, nullptr, nullptr, nullptr, MODE_NONE);
    dgate_kernel <<<NPAIR, 256>>>(gate_w, gate_b);
    axpy_kernel  <<<cgP, 256>>>(x, Vh, Vl);
    wgemm_kernel <<<ggrid, 256, SMEM_TOTAL>>>(Uh + 2*(size_t)UPLANE, Ul + 2*(size_t)UPLANE,
                                              Vh, Vl, Mbuf, 0);
    otrans_kernel<<<cgP, 256>>>(Mbuf, c1_b, bn1s, bn1b,
                                nullptr, 0, nullptr, nullptr, Vh, Vl, MODE_RELU);
    wgemm_kernel <<<ggrid, 256, SMEM_TOTAL>>>(Uh + 3*(size_t)UPLANE, Ul + 3*(size_t)UPLANE,
                                              Vh, Vl, Mbuf, 0);
    otrans_kernel<<<cgP, 256>>>(Mbuf, c2_b, bn2s, bn2b,
                                bufB, 2, pstat1, pstat2, nullptr, nullptr, MODE_NONE);
    camlp_kernel <<<NPAIR, 256>>>(ca_w1, ca_w2);
    sastats_kernel<<<sgrid, 256>>>();
    saconv_kernel<<<sgrid, 256>>>(sa_w);
    final_kernel <<<fgrid, 256>>>(adapter, dom, out);
}